// round 7
// baseline (speedup 1.0000x reference)
#include <cuda_runtime.h>
#include <cuda_bf16.h>

// Problem dims
#define IMGS 1024      // B*N = 32*32
#define HW   1024      // 32*32 pixels
#define C1O  64
#define C2O  128
#define HID  256
#define OUTD 128

// ---------------- scratch (device globals; no cudaMalloc allowed) -------------
// NOTE: these are ONLY referenced from device code. Passing a __device__ global
// as a kernel argument from host code is UB (host sees the shadow symbol) and
// was the root cause of the rel_err=1.0 failures.
__device__ float g_z1[(size_t)IMGS * C1O * HW];   // conv1 output (relu), 256 MB
__device__ float g_pool[IMGS * C2O];              // pooled conv2 output
__device__ float g_h0[IMGS * HID];                // fc output (masked)
__device__ float g_S1[32 * HID];                  // per-graph row sums of h0
__device__ float g_h1[IMGS * HID];                // sage1 output (relu)
__device__ float g_S2[32 * HID];                  // per-graph row sums of h1

// =============================== conv1 ========================================
// One block per image. 256 threads, each owns 4 consecutive pixels (same row).
__global__ void conv1_kernel(const float* __restrict__ x,
                             const float* __restrict__ w,
                             const float* __restrict__ bias) {
    __shared__ float sIn[3 * 34 * 34];   // padded input, ~13.9 KB
    __shared__ float sW[C1O * 27];       // 6.9 KB
    __shared__ float sB[C1O];

    const int img = blockIdx.x;
    const int tid = threadIdx.x;

    for (int i = tid; i < C1O * 27; i += 256) sW[i] = w[i];
    if (tid < C1O) sB[tid] = bias[tid];

    const float* xin = x + (size_t)img * 3 * HW;
    for (int i = tid; i < 3 * 34 * 34; i += 256) {
        int c = i / 1156, r = i % 1156;
        int yy = r / 34, xx = r % 34;
        int yi = yy - 1, xi = xx - 1;
        float v = 0.f;
        if ((unsigned)yi < 32u && (unsigned)xi < 32u) v = xin[c * HW + yi * 32 + xi];
        sIn[i] = v;
    }
    __syncthreads();

    const int px0 = tid * 4;
    const int y = px0 >> 5, x0 = px0 & 31;
    float* outp = g_z1 + (size_t)img * C1O * HW;

    for (int oc = 0; oc < C1O; ++oc) {
        float bb = sB[oc];
        float acc0 = bb, acc1 = bb, acc2 = bb, acc3 = bb;
        const float* wp = &sW[oc * 27];
        #pragma unroll
        for (int ic = 0; ic < 3; ++ic) {
            #pragma unroll
            for (int kh = 0; kh < 3; ++kh) {
                float a0 = sIn[ic * 1156 + (y + kh) * 34 + x0 + 0];
                float a1 = sIn[ic * 1156 + (y + kh) * 34 + x0 + 1];
                float a2 = sIn[ic * 1156 + (y + kh) * 34 + x0 + 2];
                float a3 = sIn[ic * 1156 + (y + kh) * 34 + x0 + 3];
                float a4 = sIn[ic * 1156 + (y + kh) * 34 + x0 + 4];
                float a5 = sIn[ic * 1156 + (y + kh) * 34 + x0 + 5];
                float w0 = wp[ic * 9 + kh * 3 + 0];
                float w1 = wp[ic * 9 + kh * 3 + 1];
                float w2 = wp[ic * 9 + kh * 3 + 2];
                acc0 += a0 * w0 + a1 * w1 + a2 * w2;
                acc1 += a1 * w0 + a2 * w1 + a3 * w2;
                acc2 += a2 * w0 + a3 * w1 + a4 * w2;
                acc3 += a3 * w0 + a4 * w1 + a5 * w2;
            }
        }
        float* op = outp + oc * HW + px0;
        op[0] = fmaxf(acc0, 0.f);
        op[1] = fmaxf(acc1, 0.f);
        op[2] = fmaxf(acc2, 0.f);
        op[3] = fmaxf(acc3, 0.f);
    }
}

// ====================== conv2 + bias + relu + avgpool (fused) =================
// grid (8 oc-groups, 1024 images). 256 threads. Each thread: 4 px x 16 oc accs.
// Input channels staged in STATIC smem in 8 chunks of 8 (padded 34x34).
#define ICC 8
#define NCHUNK (C1O / ICC)                   // 8

__global__ void __launch_bounds__(256, 1)
conv2_pool_kernel(const float* __restrict__ w2, const float* __restrict__ b2) {
    __shared__ float sA[ICC * 34 * 34];      // [8][34][34], 37 KB
    __shared__ float sW[16 * ICC * 12];      // [16][8][12] (9 padded to 12), 6 KB
    __shared__ float red[16][8];

    const int og  = blockIdx.x;      // 0..7
    const int img = blockIdx.y;
    const int tid = threadIdx.x;
    const int px0 = tid * 4;
    const int y = px0 >> 5, x0 = px0 & 31;

    float acc[16][4];
    #pragma unroll
    for (int o = 0; o < 16; ++o)
        #pragma unroll
        for (int p = 0; p < 4; ++p) acc[o][p] = 0.f;

    for (int cc = 0; cc < NCHUNK; ++cc) {
        __syncthreads();
        // stage padded input chunk (8 channels)
        const float* zin = g_z1 + (size_t)img * C1O * HW + (size_t)cc * ICC * HW;
        for (int i = tid; i < ICC * 1156; i += 256) {
            int c = i / 1156, r = i % 1156;
            int yy = r / 34, xx = r % 34;
            int yi = yy - 1, xi = xx - 1;
            float v = 0.f;
            if ((unsigned)yi < 32u && (unsigned)xi < 32u) v = zin[c * HW + yi * 32 + xi];
            sA[i] = v;
        }
        // stage weights for this oc-group / ic-chunk
        for (int i = tid; i < 16 * ICC * 9; i += 256) {
            int ocl = i / (ICC * 9);
            int r   = i % (ICC * 9);
            int icl = r / 9, t = r % 9;
            sW[(ocl * ICC + icl) * 12 + t] =
                w2[(((og * 16 + ocl) * C1O) + cc * ICC + icl) * 9 + t];
        }
        __syncthreads();

        #pragma unroll
        for (int ic = 0; ic < ICC; ++ic) {
            float a[3][6];
            #pragma unroll
            for (int kh = 0; kh < 3; ++kh)
                #pragma unroll
                for (int j = 0; j < 6; ++j)
                    a[kh][j] = sA[ic * 1156 + (y + kh) * 34 + x0 + j];
            #pragma unroll
            for (int ocl = 0; ocl < 16; ++ocl) {
                const float* wp = &sW[(ocl * ICC + ic) * 12];
                #pragma unroll
                for (int kh = 0; kh < 3; ++kh) {
                    float w0 = wp[kh * 3 + 0];
                    float w1 = wp[kh * 3 + 1];
                    float w2v = wp[kh * 3 + 2];
                    #pragma unroll
                    for (int p = 0; p < 4; ++p)
                        acc[ocl][p] += a[kh][p] * w0 + a[kh][p + 1] * w1 + a[kh][p + 2] * w2v;
                }
            }
        }
    }

    // bias + relu + pool (sum over the image's 1024 pixels)
    const int lane = tid & 31, wrp = tid >> 5;
    #pragma unroll
    for (int ocl = 0; ocl < 16; ++ocl) {
        float bb = b2[og * 16 + ocl];
        float s = 0.f;
        #pragma unroll
        for (int p = 0; p < 4; ++p) s += fmaxf(acc[ocl][p] + bb, 0.f);
        #pragma unroll
        for (int off = 16; off > 0; off >>= 1) s += __shfl_down_sync(0xffffffffu, s, off);
        if (lane == 0) red[ocl][wrp] = s;
    }
    __syncthreads();
    if (tid < 16) {
        float s = 0.f;
        #pragma unroll
        for (int w = 0; w < 8; ++w) s += red[tid][w];
        g_pool[img * C2O + og * 16 + tid] = s * (1.f / 1024.f);
    }
}

// =============================== fc + mask ====================================
__global__ void fc_kernel(const float* __restrict__ fw,
                          const float* __restrict__ fb,
                          const float* __restrict__ mask) {
    __shared__ float sz[C2O];
    const int r = blockIdx.x;
    const int o = threadIdx.x;     // 256 threads
    if (o < C2O) sz[o] = g_pool[r * C2O + o];
    __syncthreads();
    float accv = fb[o];
    const float* wp = fw + o * C2O;
    #pragma unroll 8
    for (int k = 0; k < C2O; k += 4) {
        float4 wv = *(const float4*)(wp + k);
        accv += sz[k] * wv.x + sz[k + 1] * wv.y + sz[k + 2] * wv.z + sz[k + 3] * wv.w;
    }
    g_h0[r * HID + o] = accv * mask[r];
}

// =============================== row sums =====================================
// STAGE 0: g_h0 -> g_S1   STAGE 1: g_h1 -> g_S2  (globals bound in device code)
template <int STAGE>
__global__ void rowsum_kernel() {
    const float* __restrict__ h = (STAGE == 0) ? g_h0 : g_h1;
    float* __restrict__ S       = (STAGE == 0) ? g_S1 : g_S2;
    const int b = blockIdx.x;
    const int d = threadIdx.x;   // HID threads
    float s = 0.f;
    #pragma unroll 8
    for (int n = 0; n < 32; ++n) s += h[(b * 32 + n) * HID + d];
    S[b * HID + d] = s;
}

// =============================== SAGE layers ==================================
// out[r][o] = sum_d agg[r][d]*lw[o][d] + lb[o] + sum_d h[r][d]*rw[o][d]
// agg[r][d] = (S[b][d] - h[r][d]) / 31
// Layer 1: h=g_h0, S=g_S1, writes g_h1 (relu). Globals bound in device code.
__global__ void sage1_kernel(const float* __restrict__ lw, const float* __restrict__ lb,
                             const float* __restrict__ rw) {
    __shared__ float sh[HID], sa[HID];
    const int r = blockIdx.x;
    const int b = r >> 5;
    {
        const int i = threadIdx.x;   // HID threads: one pass
        float hv = g_h0[r * HID + i];
        sh[i] = hv;
        sa[i] = (g_S1[b * HID + i] - hv) * (1.f / 31.f);
    }
    __syncthreads();
    const int o = threadIdx.x;
    float accv = lb[o];
    const float* lp = lw + o * HID;
    const float* rp = rw + o * HID;
    #pragma unroll 4
    for (int k = 0; k < HID; k += 4) {
        float4 lv = *(const float4*)(lp + k);
        float4 rv = *(const float4*)(rp + k);
        accv += sa[k] * lv.x + sa[k + 1] * lv.y + sa[k + 2] * lv.z + sa[k + 3] * lv.w;
        accv += sh[k] * rv.x + sh[k + 1] * rv.y + sh[k + 2] * rv.z + sh[k + 3] * rv.w;
    }
    g_h1[r * HID + o] = fmaxf(accv, 0.f);
}

// Layer 2: h=g_h1, S=g_S2, writes harness d_out (legal host-passed pointer).
__global__ void sage2_kernel(const float* __restrict__ lw, const float* __restrict__ lb,
                             const float* __restrict__ rw, float* __restrict__ out) {
    __shared__ float sh[HID], sa[HID];
    const int r = blockIdx.x;
    const int b = r >> 5;
    for (int i = threadIdx.x; i < HID; i += OUTD) {   // OUTD=128 threads: two passes
        float hv = g_h1[r * HID + i];
        sh[i] = hv;
        sa[i] = (g_S2[b * HID + i] - hv) * (1.f / 31.f);
    }
    __syncthreads();
    const int o = threadIdx.x;
    float accv = lb[o];
    const float* lp = lw + o * HID;
    const float* rp = rw + o * HID;
    #pragma unroll 4
    for (int k = 0; k < HID; k += 4) {
        float4 lv = *(const float4*)(lp + k);
        float4 rv = *(const float4*)(rp + k);
        accv += sa[k] * lv.x + sa[k + 1] * lv.y + sa[k + 2] * lv.z + sa[k + 3] * lv.w;
        accv += sh[k] * rv.x + sh[k + 1] * rv.y + sh[k + 2] * rv.z + sh[k + 3] * rv.w;
    }
    out[r * OUTD + o] = accv;
}

// ================================ launch ======================================
// Pure kernel launches only; graph-capturable. No device-global symbol is ever
// passed from host. Inputs bound BY ELEMENT COUNT (robust to metadata order):
//   unique:  x=3145728, mask=1024, conv1_w=1728, conv1_b=64, conv2_w=73728
//   by occurrence (same relative order under insertion OR alphabetical order):
//     128:   conv2_b, s2_lb          256:   fc_b, s1_lb
//     32768: fc_w, s2_lw, s2_rw      65536: s1_lw, s1_rw
extern "C" void kernel_launch(void* const* d_in, const int* in_sizes, int n_in,
                              void* d_out, int out_size) {
    const float *x = 0, *mask = 0, *c1w = 0, *c1b = 0, *c2w = 0;
    const float *c2b = 0, *s2lb = 0;            // 128-group
    const float *fcb = 0, *s1lb = 0;            // 256-group
    const float *fcw = 0, *s2lw = 0, *s2rw = 0; // 32768-group
    const float *s1lw = 0, *s1rw = 0;           // 65536-group
    int n128 = 0, n256 = 0, n32k = 0, n64k = 0;

    for (int i = 0; i < n_in; ++i) {
        const float* p = (const float*)d_in[i];
        switch (in_sizes[i]) {
            case 3145728: x = p; break;
            case 1024:    mask = p; break;
            case 1728:    c1w = p; break;
            case 64:      c1b = p; break;
            case 73728:   c2w = p; break;
            case 128:     if (n128++ == 0) c2b = p; else s2lb = p; break;
            case 256:     if (n256++ == 0) fcb = p; else s1lb = p; break;
            case 32768:
                if (n32k == 0) fcw = p; else if (n32k == 1) s2lw = p; else s2rw = p;
                ++n32k; break;
            case 65536:
                if (n64k++ == 0) s1lw = p; else s1rw = p; break;
            default: break;
        }
    }

    float* out = (float*)d_out;

    conv1_kernel<<<IMGS, 256>>>(x, c1w, c1b);

    dim3 g2(8, IMGS);
    conv2_pool_kernel<<<g2, 256>>>(c2w, c2b);

    fc_kernel<<<IMGS, 256>>>(fcw, fcb, mask);

    rowsum_kernel<0><<<32, HID>>>();
    sage1_kernel<<<IMGS, HID>>>(s1lw, s1lb, s1rw);
    rowsum_kernel<1><<<32, HID>>>();
    sage2_kernel<<<IMGS, OUTD>>>(s2lw, s2lb, s2rw, out);
    (void)out_size;
}